// round 1
// baseline (speedup 1.0000x reference)
#include <cuda_runtime.h>
#include <math.h>

#define Bn 2
#define Sn 2048
#define Dn 2048
#define Hn 16
#define DHn 128
#define DRn 64
#define DCKVn 512
#define DCQn 1536
#define Mn (Bn*Sn)   // 4096 rows for every GEMM

// ---------------- scratch (device globals; no allocation allowed) ----------------
__device__ float g_kvc [(size_t)Mn*DCKVn];
__device__ float g_qc  [(size_t)Mn*DCQn];
__device__ float g_kcnt[(size_t)Mn*Hn*DHn];
__device__ float g_v   [(size_t)Mn*Hn*DHn];
__device__ float g_qcnt[(size_t)Mn*Hn*DHn];
__device__ float g_kr  [(size_t)Mn*Hn*DRn];
__device__ float g_qr  [(size_t)Mn*Hn*DRn];
__device__ float g_attn[(size_t)Mn*Hn*DHn];

// ---------------- generic C[M,N] = A[M,K] @ W[N,K]^T + bias ----------------
// 128x128 block, BK=8, 256 threads, 8x8 microtile. Smem staged transposed
// ([k][row]) so inner-loop reads are float4 and conflict-free.
__global__ __launch_bounds__(256) void gemm_bias_kernel(
    const float* __restrict__ A, const float* __restrict__ W,
    const float* __restrict__ bias, float* __restrict__ C,
    int M, int N, int K)
{
    __shared__ float As[8][132];
    __shared__ float Bs[8][132];
    const int tid = threadIdx.x;
    const int tx = tid & 15, ty = tid >> 4;
    const int m0 = blockIdx.y << 7, n0 = blockIdx.x << 7;
    const int lr = tid >> 1;              // 0..127 row within tile
    const int lk = (tid & 1) << 2;        // 0 or 4
    const float* Ap = A + (size_t)(m0 + lr) * K + lk;
    const float* Wp = W + (size_t)(n0 + lr) * K + lk;

    float acc[8][8];
#pragma unroll
    for (int i = 0; i < 8; i++)
#pragma unroll
        for (int j = 0; j < 8; j++) acc[i][j] = 0.f;

    for (int k0 = 0; k0 < K; k0 += 8) {
        float4 av = *(const float4*)(Ap + k0);
        float4 wv = *(const float4*)(Wp + k0);
        __syncthreads();
        As[lk+0][lr] = av.x; As[lk+1][lr] = av.y; As[lk+2][lr] = av.z; As[lk+3][lr] = av.w;
        Bs[lk+0][lr] = wv.x; Bs[lk+1][lr] = wv.y; Bs[lk+2][lr] = wv.z; Bs[lk+3][lr] = wv.w;
        __syncthreads();
#pragma unroll
        for (int kk = 0; kk < 8; kk++) {
            float a[8], b[8];
            *(float4*)(a  ) = *(const float4*)(&As[kk][ty*8]);
            *(float4*)(a+4) = *(const float4*)(&As[kk][ty*8+4]);
            *(float4*)(b  ) = *(const float4*)(&Bs[kk][tx*8]);
            *(float4*)(b+4) = *(const float4*)(&Bs[kk][tx*8+4]);
#pragma unroll
            for (int i = 0; i < 8; i++)
#pragma unroll
                for (int j = 0; j < 8; j++)
                    acc[i][j] = fmaf(a[i], b[j], acc[i][j]);
        }
    }

    float bv[8];
    *(float4*)(bv  ) = *(const float4*)(bias + n0 + tx*8);
    *(float4*)(bv+4) = *(const float4*)(bias + n0 + tx*8 + 4);
#pragma unroll
    for (int i = 0; i < 8; i++) {
        float* Cp = C + (size_t)(m0 + ty*8 + i) * N + n0 + tx*8;
        float4 o0 = make_float4(acc[i][0]+bv[0], acc[i][1]+bv[1], acc[i][2]+bv[2], acc[i][3]+bv[3]);
        float4 o1 = make_float4(acc[i][4]+bv[4], acc[i][5]+bv[5], acc[i][6]+bv[6], acc[i][7]+bv[7]);
        *(float4*)(Cp    ) = o0;
        *(float4*)(Cp + 4) = o1;
    }
}

// ---------------- rotate-half RoPE, in place on t: [B,S,H,DR] ----------------
__global__ void rope_kernel(float* __restrict__ t, int total)
{
    int idx = blockIdx.x * blockDim.x + threadIdx.x;
    if (idx >= total) return;
    int j   = idx & 31;            // 0..DR/2-1
    int rem = idx >> 5;            // (b*S+s)*H + h
    int bs  = rem >> 4;            // b*S+s   (H=16)
    int s   = bs & (Sn - 1);
    float inv_freq = 1.0f / powf(10000.0f, (float)(2 * j) / (float)DRn);
    float ang = (float)s * inv_freq;
    float sv, cv;
    sincosf(ang, &sv, &cv);        // precise-range version (angles up to ~2047 rad)
    float* p = t + (size_t)rem * DRn;
    float t1 = p[j], t2 = p[j + 32];
    p[j]      = t1 * cv - t2 * sv;
    p[j + 32] = t2 * cv + t1 * sv;
}

// ---------------- causal flash attention, fp32 ----------------
// grid (S/64, B*H). 64x64 tiles, online softmax, dqk=192, dv=128.
#define AT_SQK 193   // 192 + 1 pad
#define AT_SP  68
#define ATTN_SMEM ((64*AT_SQK*2 + 64*128 + 64*AT_SP) * 4)

__global__ __launch_bounds__(256) void attn_kernel(
    const float* __restrict__ qcnt, const float* __restrict__ qr,
    const float* __restrict__ kcnt, const float* __restrict__ kr,
    const float* __restrict__ v, float* __restrict__ outp)
{
    extern __shared__ float sm[];
    float* Qs = sm;                  // [64][193]
    float* Ks = Qs + 64 * AT_SQK;    // [64][193]
    float* Vs = Ks + 64 * AT_SQK;    // [64][128]
    float* Ps = Vs + 64 * 128;       // [64][68]

    const int tid = threadIdx.x;
    const int tx = tid & 15, ty = tid >> 4;
    const int qb = blockIdx.x;
    const int b  = blockIdx.y >> 4;  // H = 16
    const int h  = blockIdx.y & 15;
    const int q0 = qb * 64;
    const float scale = rsqrtf((float)(DHn + DRn));

    // Q tile (prescaled by softmax scale)
    for (int idx = tid; idx < 64 * 48; idx += 256) {
        int r = idx / 48, c4 = idx % 48;
        float4 val;
        if (c4 < 32)
            val = *(const float4*)(qcnt + (size_t)(b*Sn + q0 + r) * (Hn*DHn) + h*DHn + c4*4);
        else
            val = *(const float4*)(qr   + (size_t)(b*Sn + q0 + r) * (Hn*DRn) + h*DRn + (c4-32)*4);
        float* dst = Qs + r * AT_SQK + c4 * 4;
        dst[0] = val.x * scale; dst[1] = val.y * scale;
        dst[2] = val.z * scale; dst[3] = val.w * scale;
    }

    float m[4], l[4], acc[4][8];
#pragma unroll
    for (int i = 0; i < 4; i++) {
        m[i] = -3.0e38f; l[i] = 0.f;
#pragma unroll
        for (int j = 0; j < 8; j++) acc[i][j] = 0.f;
    }

    for (int kb = 0; kb <= qb; kb++) {
        const int k0 = kb * 64;
        __syncthreads();   // previous iteration's readers of Ks/Vs/Ps are done
        for (int idx = tid; idx < 64 * 48; idx += 256) {
            int r = idx / 48, c4 = idx % 48;
            float4 val;
            if (c4 < 32)
                val = *(const float4*)(kcnt + (size_t)(b*Sn + k0 + r) * (Hn*DHn) + h*DHn + c4*4);
            else
                val = *(const float4*)(kr   + (size_t)(b*Sn + k0 + r) * (Hn*DRn) + h*DRn + (c4-32)*4);
            float* dst = Ks + r * AT_SQK + c4 * 4;
            dst[0] = val.x; dst[1] = val.y; dst[2] = val.z; dst[3] = val.w;
        }
        for (int idx = tid; idx < 64 * 32; idx += 256) {
            int r = idx >> 5, c4 = idx & 31;
            *(float4*)(Vs + r*128 + c4*4) =
                *(const float4*)(v + (size_t)(b*Sn + k0 + r) * (Hn*DHn) + h*DHn + c4*4);
        }
        __syncthreads();

        float s[4][4];
#pragma unroll
        for (int i = 0; i < 4; i++)
#pragma unroll
            for (int j = 0; j < 4; j++) s[i][j] = 0.f;

        const float* Qp = Qs + (ty*4) * AT_SQK;
        const float* Kp = Ks + (tx*4) * AT_SQK;
#pragma unroll 8
        for (int k = 0; k < 192; k++) {
            float a0 = Qp[k], a1 = Qp[AT_SQK + k], a2 = Qp[2*AT_SQK + k], a3 = Qp[3*AT_SQK + k];
            float b0 = Kp[k], b1 = Kp[AT_SQK + k], b2 = Kp[2*AT_SQK + k], b3 = Kp[3*AT_SQK + k];
            s[0][0] = fmaf(a0,b0,s[0][0]); s[0][1] = fmaf(a0,b1,s[0][1]);
            s[0][2] = fmaf(a0,b2,s[0][2]); s[0][3] = fmaf(a0,b3,s[0][3]);
            s[1][0] = fmaf(a1,b0,s[1][0]); s[1][1] = fmaf(a1,b1,s[1][1]);
            s[1][2] = fmaf(a1,b2,s[1][2]); s[1][3] = fmaf(a1,b3,s[1][3]);
            s[2][0] = fmaf(a2,b0,s[2][0]); s[2][1] = fmaf(a2,b1,s[2][1]);
            s[2][2] = fmaf(a2,b2,s[2][2]); s[2][3] = fmaf(a2,b3,s[2][3]);
            s[3][0] = fmaf(a3,b0,s[3][0]); s[3][1] = fmaf(a3,b1,s[3][1]);
            s[3][2] = fmaf(a3,b2,s[3][2]); s[3][3] = fmaf(a3,b3,s[3][3]);
        }

        if (kb == qb) {   // diagonal block: mask strict-upper
#pragma unroll
            for (int i = 0; i < 4; i++)
#pragma unroll
                for (int j = 0; j < 4; j++)
                    if (tx*4 + j > ty*4 + i) s[i][j] = -1e9f;
        }

#pragma unroll
        for (int i = 0; i < 4; i++) {
            float rmax = fmaxf(fmaxf(s[i][0], s[i][1]), fmaxf(s[i][2], s[i][3]));
#pragma unroll
            for (int off = 8; off >= 1; off >>= 1)
                rmax = fmaxf(rmax, __shfl_xor_sync(0xffffffffu, rmax, off, 16));
            float mn = fmaxf(m[i], rmax);
            float alpha = __expf(m[i] - mn);
            float rs = 0.f;
#pragma unroll
            for (int j = 0; j < 4; j++) { s[i][j] = __expf(s[i][j] - mn); rs += s[i][j]; }
#pragma unroll
            for (int off = 8; off >= 1; off >>= 1)
                rs += __shfl_xor_sync(0xffffffffu, rs, off, 16);
            l[i] = l[i] * alpha + rs;
            m[i] = mn;
#pragma unroll
            for (int j = 0; j < 8; j++) acc[i][j] *= alpha;
            float* pp = Ps + (ty*4 + i) * AT_SP + tx*4;
            pp[0] = s[i][0]; pp[1] = s[i][1]; pp[2] = s[i][2]; pp[3] = s[i][3];
        }
        __syncthreads();

        const float* Vp = Vs + tx*8;
#pragma unroll 4
        for (int c = 0; c < 64; c++) {
            float p0 = Ps[(ty*4+0)*AT_SP + c];
            float p1 = Ps[(ty*4+1)*AT_SP + c];
            float p2 = Ps[(ty*4+2)*AT_SP + c];
            float p3 = Ps[(ty*4+3)*AT_SP + c];
            float vv[8];
            *(float4*)(vv  ) = *(const float4*)(Vp + c*128);
            *(float4*)(vv+4) = *(const float4*)(Vp + c*128 + 4);
#pragma unroll
            for (int j = 0; j < 8; j++) {
                acc[0][j] = fmaf(p0, vv[j], acc[0][j]);
                acc[1][j] = fmaf(p1, vv[j], acc[1][j]);
                acc[2][j] = fmaf(p2, vv[j], acc[2][j]);
                acc[3][j] = fmaf(p3, vv[j], acc[3][j]);
            }
        }
    }

#pragma unroll
    for (int i = 0; i < 4; i++) {
        float inv = 1.0f / l[i];
        float* op = outp + (size_t)(b*Sn + q0 + ty*4 + i) * (Hn*DHn) + h*DHn + tx*8;
        float4 o0 = make_float4(acc[i][0]*inv, acc[i][1]*inv, acc[i][2]*inv, acc[i][3]*inv);
        float4 o1 = make_float4(acc[i][4]*inv, acc[i][5]*inv, acc[i][6]*inv, acc[i][7]*inv);
        *(float4*)(op    ) = o0;
        *(float4*)(op + 4) = o1;
    }
}

// ---------------- launch ----------------
extern "C" void kernel_launch(void* const* d_in, const int* in_sizes, int n_in,
                              void* d_out, int out_size)
{
    const float* x   = (const float*)d_in[0];
    const float* Wkd = (const float*)d_in[1];
    const float* bkd = (const float*)d_in[2];
    const float* Wqd = (const float*)d_in[3];
    const float* bqd = (const float*)d_in[4];
    const float* Wku = (const float*)d_in[5];
    const float* bku = (const float*)d_in[6];
    const float* Wvu = (const float*)d_in[7];
    const float* bvu = (const float*)d_in[8];
    const float* Wqu = (const float*)d_in[9];
    const float* bqu = (const float*)d_in[10];
    const float* Wkr = (const float*)d_in[11];
    const float* bkr = (const float*)d_in[12];
    const float* Wqr = (const float*)d_in[13];
    const float* bqr = (const float*)d_in[14];
    const float* Wo  = (const float*)d_in[15];
    const float* bo  = (const float*)d_in[16];

    float *kvc, *qc, *kcnt, *vv, *qcnt, *kr, *qr, *attn;
    cudaGetSymbolAddress((void**)&kvc,  g_kvc);
    cudaGetSymbolAddress((void**)&qc,   g_qc);
    cudaGetSymbolAddress((void**)&kcnt, g_kcnt);
    cudaGetSymbolAddress((void**)&vv,   g_v);
    cudaGetSymbolAddress((void**)&qcnt, g_qcnt);
    cudaGetSymbolAddress((void**)&kr,   g_kr);
    cudaGetSymbolAddress((void**)&qr,   g_qr);
    cudaGetSymbolAddress((void**)&attn, g_attn);

    dim3 thr(256);
    // compress
    gemm_bias_kernel<<<dim3(DCKVn/128, Mn/128), thr>>>(x,  Wkd, bkd, kvc,  Mn, DCKVn, Dn);
    gemm_bias_kernel<<<dim3(DCQn /128, Mn/128), thr>>>(x,  Wqd, bqd, qc,   Mn, DCQn,  Dn);
    // up-project
    gemm_bias_kernel<<<dim3((Hn*DHn)/128, Mn/128), thr>>>(kvc, Wku, bku, kcnt, Mn, Hn*DHn, DCKVn);
    gemm_bias_kernel<<<dim3((Hn*DHn)/128, Mn/128), thr>>>(kvc, Wvu, bvu, vv,   Mn, Hn*DHn, DCKVn);
    gemm_bias_kernel<<<dim3((Hn*DHn)/128, Mn/128), thr>>>(qc,  Wqu, bqu, qcnt, Mn, Hn*DHn, DCQn);
    gemm_bias_kernel<<<dim3((Hn*DRn)/128, Mn/128), thr>>>(x,   Wkr, bkr, kr,   Mn, Hn*DRn, Dn);
    gemm_bias_kernel<<<dim3((Hn*DRn)/128, Mn/128), thr>>>(qc,  Wqr, bqr, qr,   Mn, Hn*DRn, DCQn);
    // rope (in place)
    int rope_total = Mn * Hn * (DRn / 2);
    rope_kernel<<<(rope_total + 255) / 256, 256>>>(kr, rope_total);
    rope_kernel<<<(rope_total + 255) / 256, 256>>>(qr, rope_total);
    // attention
    cudaFuncSetAttribute(attn_kernel, cudaFuncAttributeMaxDynamicSharedMemorySize, ATTN_SMEM);
    attn_kernel<<<dim3(Sn/64, Bn*Hn), thr, ATTN_SMEM>>>(qcnt, qr, kcnt, kr, vv, attn);
    // output projection
    gemm_bias_kernel<<<dim3(Dn/128, Mn/128), thr>>>(attn, Wo, bo, (float*)d_out, Mn, Dn, Dn);
}